// round 1
// baseline (speedup 1.0000x reference)
#include <cuda_runtime.h>
#include <math.h>
#include <stdint.h>

// Problem constants
#define BB 8
#define SS 8192
#define DD 64
#define HH 8
#define NBUCK 128            // buckets per hash round
#define NCHUNK 1024          // chunks per batch (H * S / 64)
#define SELF_VAL -5e4f

// ---------------- scratch (device globals; no allocations allowed) ----------
__device__ int   g_bucket[BB * HH * SS];                 // 2 MB
__device__ int   g_st[BB * HH * SS];                     // 2 MB  sorted token ids
__device__ float g_logits[BB * HH * SS];                 // 2 MB  per-round lse
__device__ float g_o[(size_t)BB * HH * SS * DD];         // 128 MB per-round outputs

// ---------------- kernel 1: LSH hashing -------------------------------------
// grid: B*H*(S/128) = 4096 blocks, 128 threads (one token per thread)
__global__ void hash_kernel(const float* __restrict__ qk,
                            const float* __restrict__ rot)
{
    __shared__ float rot_s[64 * 68];   // rot_s[i][f], padded stride 68

    int blk  = blockIdx.x;
    int tile = blk & 63;
    int h    = (blk >> 6) & 7;
    int b    = blk >> 9;
    int tid  = threadIdx.x;

    // load rotation slice transposed: rot_s[i*68+f] = rotations[f, h, i]
    for (int idx = tid; idx < 4096; idx += 128) {
        int f = idx >> 6, i = idx & 63;
        rot_s[i * 68 + f] = rot[f * (HH * 64) + h * 64 + i];
    }
    __syncthreads();

    int t = tile * 128 + tid;
    const float4* q4 = (const float4*)(qk + ((size_t)b * SS + t) * DD);
    float4 q[16];
#pragma unroll
    for (int k = 0; k < 16; k++) q[k] = q4[k];

    float maxv = -1e30f, minv = 1e30f;
    int maxi = 0, mini = 0;
    for (int i = 0; i < 64; i++) {
        const float4* rr = (const float4*)(rot_s + i * 68);
        float4 a = make_float4(0.f, 0.f, 0.f, 0.f);
#pragma unroll
        for (int k = 0; k < 16; k++) {
            float4 r = rr[k];
            a.x += q[k].x * r.x; a.y += q[k].y * r.y;
            a.z += q[k].z * r.z; a.w += q[k].w * r.w;
        }
        float vdot = (a.x + a.y) + (a.z + a.w);
        if (vdot > maxv) { maxv = vdot; maxi = i; }   // strict > keeps first index
        if (vdot < minv) { minv = vdot; mini = i; }
    }
    // argmax over concat([r, -r]): first half wins ties (>=)
    int bucket = (maxv >= -minv) ? maxi : 64 + mini;
    g_bucket[(b * HH + h) * SS + t] = bucket;
}

// ---------------- kernel 2: stable counting sort per (b,h) ------------------
// grid: 64 blocks, 128 threads. Each thread owns a 64-token segment.
__global__ void sort_kernel()
{
    __shared__ unsigned short cnt[128 * 128];  // [segment][bucket]
    __shared__ int tot[128];
    __shared__ int base[128];

    int bh = blockIdx.x;
    const int* gb = g_bucket + bh * SS;
    int* out = g_st + bh * SS;
    int s = threadIdx.x;

    for (int k = 0; k < 128; k++) cnt[s * 128 + k] = 0;
    __syncthreads();

    for (int k = 0; k < 64; k++) {
        int bkt = gb[s * 64 + k];
        cnt[s * 128 + bkt]++;
    }
    __syncthreads();

    // per-bucket exclusive prefix over segments (thread s handles bucket s)
    {
        int run = 0;
        for (int seg = 0; seg < 128; seg++) {
            int vv = cnt[seg * 128 + s];
            cnt[seg * 128 + s] = (unsigned short)run;
            run += vv;
        }
        tot[s] = run;
    }
    __syncthreads();
    if (s == 0) {
        int r = 0;
        for (int k = 0; k < 128; k++) { base[k] = r; r += tot[k]; }
    }
    __syncthreads();

    // stable placement (each thread sequential over its segment)
    for (int k = 0; k < 64; k++) {
        int t = s * 64 + k;
        int bkt = gb[t];
        int pos = base[bkt] + cnt[s * 128 + bkt];
        cnt[s * 128 + bkt]++;
        out[pos] = t;
    }
}

// ---------------- kernel 3: bucketed attention ------------------------------
// grid: B*1024 = 8192 blocks, 256 threads.
// smem: ks 128x68 + vs 128x68 + dots 64x132 + invn 128 + ids 128 = 104448 B
#define ATTN_SMEM 104448
__global__ void __launch_bounds__(256, 2)
attn_kernel(const float* __restrict__ qk, const float* __restrict__ v)
{
    extern __shared__ float sm[];
    float* ks   = sm;                       // raw qk rows (128 x stride 68)
    float* vs   = ks + 128 * 68;
    float* dots = vs + 128 * 68;            // 64 x stride 132
    float* invn = dots + 64 * 132;          // 128
    int*   ids  = (int*)(invn + 128);       // 128

    int b  = blockIdx.x >> 10;
    int c  = blockIdx.x & 1023;
    int pc = (c + NCHUNK - 1) & (NCHUNK - 1);
    int tid = threadIdx.x;

    if (tid < 128) {
        int p = (tid < 64) ? (c * 64 + tid) : (pc * 64 + (tid - 64));
        ids[tid] = g_st[b * (HH * SS) + p];
    }
    __syncthreads();

    // gather K(=qk rows) and V rows
    const float4* qk4 = (const float4*)(qk + (size_t)b * SS * DD);
    const float4* v4  = (const float4*)(v  + (size_t)b * SS * DD);
    for (int idx = tid; idx < 2048; idx += 256) {
        int r = idx >> 4, f = idx & 15;
        int tok = ids[r];
        ((float4*)ks)[r * 17 + f] = qk4[tok * 16 + f];
        ((float4*)vs)[r * 17 + f] = v4[tok * 16 + f];
    }
    __syncthreads();

    if (tid < 128) {
        const float4* row = (const float4*)ks + tid * 17;
        float ssum = 0.f;
#pragma unroll
        for (int k = 0; k < 16; k++) {
            float4 a = row[k];
            ssum += a.x * a.x + a.y * a.y + a.z * a.z + a.w * a.w;
        }
        invn[tid] = 1.0f / (sqrtf(ssum) + 1e-6f);
    }
    __syncthreads();

    int qi = tid >> 2, kq = tid & 3;

    // Q row in registers
    float4 q[16];
    {
        const float4* row = (const float4*)ks + qi * 17;
#pragma unroll
        for (int k = 0; k < 16; k++) q[k] = row[k];
    }
    int idq = ids[qi];

    // dots: each thread does 32 keys
    for (int kk = 0; kk < 32; kk++) {
        int kj = kq * 32 + kk;
        const float4* krow = (const float4*)ks + kj * 17;
        float4 a = make_float4(0.f, 0.f, 0.f, 0.f);
#pragma unroll
        for (int k = 0; k < 16; k++) {
            float4 r = krow[k];
            a.x += q[k].x * r.x; a.y += q[k].y * r.y;
            a.z += q[k].z * r.z; a.w += q[k].w * r.w;
        }
        float val = ((a.x + a.y) + (a.z + a.w)) * invn[kj] * 0.125f;
        if (ids[kj] == idq) val = SELF_VAL;
        dots[qi * 132 + kj] = val;
    }
    __syncthreads();

    // softmax + lse per row
    if (tid < 64) {
        float* row = dots + tid * 132;
        float m = -1e30f;
        for (int j = 0; j < 128; j++) m = fmaxf(m, row[j]);
        float sum = 0.f;
        for (int j = 0; j < 128; j++) {
            float e = __expf(row[j] - m);
            row[j] = e;
            sum += e;
        }
        float inv = 1.0f / sum;
        for (int j = 0; j < 128; j++) row[j] *= inv;
        float lse = m + __logf(sum);
        int h = (c * 64 + tid) >> 13;
        g_logits[b * (HH * SS) + h * SS + ids[tid]] = lse;
    }
    __syncthreads();

    // PV: thread (qi, dg) computes 16 output dims
    int dg = tid & 3;
    float4 acc[4];
#pragma unroll
    for (int k = 0; k < 4; k++) acc[k] = make_float4(0.f, 0.f, 0.f, 0.f);

    const float* prow = dots + qi * 132;
    for (int j = 0; j < 128; j++) {
        float p = prow[j];
        const float4* vrow = (const float4*)vs + j * 17 + dg * 4;
#pragma unroll
        for (int k = 0; k < 4; k++) {
            float4 w = vrow[k];
            acc[k].x += p * w.x; acc[k].y += p * w.y;
            acc[k].z += p * w.z; acc[k].w += p * w.w;
        }
    }
    int h = (c * 64 + qi) >> 13;
    float4* orow = (float4*)(g_o + ((size_t)b * (HH * SS) + h * SS + ids[qi]) * DD) + dg * 4;
#pragma unroll
    for (int k = 0; k < 4; k++) orow[k] = acc[k];
}

// ---------------- kernel 4: combine hash rounds ------------------------------
// grid: B*S*D / 256 = 16384 blocks
__global__ void combine_kernel(float* __restrict__ out)
{
    int gidx = blockIdx.x * 256 + threadIdx.x;   // [0, 4194304)
    int d = gidx & 63;
    int g = gidx >> 6;        // token index within B*S
    int b = g >> 13;
    int s = g & (SS - 1);

    float l[HH];
    float m = -1e30f;
#pragma unroll
    for (int h = 0; h < HH; h++) {
        l[h] = g_logits[b * (HH * SS) + h * SS + s];
        m = fmaxf(m, l[h]);
    }
    float sum = 0.f;
#pragma unroll
    for (int h = 0; h < HH; h++) { l[h] = __expf(l[h] - m); sum += l[h]; }
    float inv = 1.0f / sum;

    float acc = 0.f;
#pragma unroll
    for (int h = 0; h < HH; h++) {
        acc += l[h] * inv * g_o[((size_t)b * (HH * SS) + h * SS + s) * DD + d];
    }
    out[gidx] = acc;
}

// ---------------- launcher ---------------------------------------------------
extern "C" void kernel_launch(void* const* d_in, const int* in_sizes, int n_in,
                              void* d_out, int out_size)
{
    const float* qk  = (const float*)d_in[0];
    const float* v   = (const float*)d_in[1];
    const float* rot = (const float*)d_in[2];
    float* out = (float*)d_out;
    (void)in_sizes; (void)n_in; (void)out_size;

    cudaFuncSetAttribute(attn_kernel,
                         cudaFuncAttributeMaxDynamicSharedMemorySize, ATTN_SMEM);

    hash_kernel<<<BB * HH * (SS / 128), 128>>>(qk, rot);
    sort_kernel<<<BB * HH, 128>>>();
    attn_kernel<<<BB * NCHUNK, 256, ATTN_SMEM>>>(qk, v);
    combine_kernel<<<(BB * SS * DD) / 256, 256>>>(out);
}

// round 2
// speedup vs baseline: 2.5155x; 2.5155x over previous
#include <cuda_runtime.h>
#include <math.h>
#include <stdint.h>

// Problem constants
#define BB 8
#define SS 8192
#define DD 64
#define HH 8
#define NCHUNK 1024          // chunks per batch (H * S / 64)
#define SELF_VAL -5e4f

#define KSTR 68              // K/V row stride in floats (17 float4)
#define PSTR 132             // P row stride in floats

typedef unsigned long long u64;

// ---------------- packed f32x2 helpers --------------------------------------
__device__ __forceinline__ void fma2(u64& d, u64 a, u64 b) {
    asm("fma.rn.f32x2 %0, %1, %2, %0;" : "+l"(d) : "l"(a), "l"(b));
}
__device__ __forceinline__ u64 pack2(float x) {
    u64 r; unsigned u = __float_as_uint(x);
    asm("mov.b64 %0, {%1, %1};" : "=l"(r) : "r"(u));
    return r;
}
__device__ __forceinline__ float hadd2(u64 a) {
    unsigned lo, hi;
    asm("mov.b64 {%0, %1}, %2;" : "=r"(lo), "=r"(hi) : "l"(a));
    return __uint_as_float(lo) + __uint_as_float(hi);
}

// ---------------- scratch (device globals; no allocations allowed) ----------
__device__ int   g_bucket[BB * HH * SS];                 // 2 MB
__device__ int   g_st[BB * HH * SS];                     // 2 MB  sorted token ids
__device__ float g_logits[BB * HH * SS];                 // 2 MB  per-round lse
__device__ float g_o[(size_t)BB * HH * SS * DD];         // 128 MB per-round outputs

// ---------------- kernel 1: LSH hashing -------------------------------------
// grid: B*H*(S/128) = 4096 blocks, 128 threads (one token per thread)
__global__ void hash_kernel(const float* __restrict__ qk,
                            const float* __restrict__ rot)
{
    __shared__ float rot_s[64 * KSTR];   // rot_s[i][f], padded stride 68

    int blk  = blockIdx.x;
    int tile = blk & 63;
    int h    = (blk >> 6) & 7;
    int b    = blk >> 9;
    int tid  = threadIdx.x;

    // load rotation slice transposed: rot_s[i*68+f] = rotations[f, h, i]
    for (int idx = tid; idx < 4096; idx += 128) {
        int f = idx >> 6, i = idx & 63;
        rot_s[i * KSTR + f] = rot[f * (HH * 64) + h * 64 + i];
    }
    __syncthreads();

    int t = tile * 128 + tid;
    const ulonglong2* q8 = (const ulonglong2*)(qk + ((size_t)b * SS + t) * DD);
    u64 q[32];
#pragma unroll
    for (int k = 0; k < 16; k++) {
        ulonglong2 w = q8[k];
        q[2 * k] = w.x; q[2 * k + 1] = w.y;
    }

    float maxv = -1e30f, minv = 1e30f;
    int maxi = 0, mini = 0;
    for (int i = 0; i < 64; i++) {
        const ulonglong2* rr = (const ulonglong2*)(rot_s + i * KSTR);
        u64 a0 = 0, a1 = 0;
#pragma unroll
        for (int k = 0; k < 16; k++) {
            ulonglong2 r = rr[k];
            fma2(a0, q[2 * k],     r.x);
            fma2(a1, q[2 * k + 1], r.y);
        }
        float vdot = hadd2(a0) + hadd2(a1);
        if (vdot > maxv) { maxv = vdot; maxi = i; }   // strict > keeps first index
        if (vdot < minv) { minv = vdot; mini = i; }
    }
    // argmax over concat([r, -r]): first half wins ties (>=)
    int bucket = (maxv >= -minv) ? maxi : 64 + mini;
    g_bucket[(b * HH + h) * SS + t] = bucket;
}

// ---------------- kernel 2: stable counting sort per (b,h) ------------------
// grid: 64 blocks, 128 threads. Each thread owns a 64-token segment.
__global__ void sort_kernel()
{
    __shared__ unsigned short cnt[128 * 128];  // [segment][bucket]
    __shared__ int tot[128];
    __shared__ int base[128];

    int bh = blockIdx.x;
    const int* gb = g_bucket + bh * SS;
    int* out = g_st + bh * SS;
    int s = threadIdx.x;

    for (int k = 0; k < 128; k++) cnt[s * 128 + k] = 0;
    __syncthreads();

    for (int k = 0; k < 64; k++) {
        int bkt = gb[s * 64 + k];
        cnt[s * 128 + bkt]++;
    }
    __syncthreads();

    // per-bucket exclusive prefix over segments (thread s handles bucket s)
    {
        int run = 0;
        for (int seg = 0; seg < 128; seg++) {
            int vv = cnt[seg * 128 + s];
            cnt[seg * 128 + s] = (unsigned short)run;
            run += vv;
        }
        tot[s] = run;
    }
    __syncthreads();
    if (s == 0) {
        int r = 0;
        for (int k = 0; k < 128; k++) { base[k] = r; r += tot[k]; }
    }
    __syncthreads();

    // stable placement (each thread sequential over its segment)
    for (int k = 0; k < 64; k++) {
        int t = s * 64 + k;
        int bkt = gb[t];
        int pos = base[bkt] + cnt[s * 128 + bkt];
        cnt[s * 128 + bkt]++;
        out[pos] = t;
    }
}

// ---------------- kernel 3: bucketed attention ------------------------------
// grid: B*1024 = 8192 blocks, 256 threads.
// smem: ks 128x68 + vs 128x68 + P 64x132 + invn 128 + ids 128 = 104448 B
#define ATTN_SMEM 104448
__global__ void __launch_bounds__(256, 2)
attn_kernel(const float* __restrict__ qk, const float* __restrict__ v)
{
    extern __shared__ float sm[];
    float* ks   = sm;                       // raw qk rows (128 x stride 68)
    float* vs   = ks + 128 * KSTR;
    float* P    = vs + 128 * KSTR;          // 64 x stride 132 (softmax probs)
    float* invn = P + 64 * PSTR;            // 128
    int*   ids  = (int*)(invn + 128);       // 128

    int b  = blockIdx.x >> 10;
    int c  = blockIdx.x & 1023;
    int pc = (c + NCHUNK - 1) & (NCHUNK - 1);
    int tid = threadIdx.x;

    if (tid < 128) {
        int p = (tid < 64) ? (c * 64 + tid) : (pc * 64 + (tid - 64));
        ids[tid] = g_st[b * (HH * SS) + p];
    }
    __syncthreads();

    // gather K(=qk rows) and V rows
    const float4* qk4 = (const float4*)(qk + (size_t)b * SS * DD);
    const float4* v4  = (const float4*)(v  + (size_t)b * SS * DD);
    for (int idx = tid; idx < 2048; idx += 256) {
        int r = idx >> 4, f = idx & 15;
        int tok = ids[r];
        ((float4*)ks)[r * 17 + f] = qk4[tok * 16 + f];
        ((float4*)vs)[r * 17 + f] = v4[tok * 16 + f];
    }
    __syncthreads();

    // inverse key norms
    if (tid < 128) {
        const float4* row = (const float4*)ks + tid * 17;
        float ssum = 0.f;
#pragma unroll
        for (int k = 0; k < 16; k++) {
            float4 a = row[k];
            ssum += a.x * a.x + a.y * a.y + a.z * a.z + a.w * a.w;
        }
        invn[tid] = 1.0f / (sqrtf(ssum) + 1e-6f);
    }
    __syncthreads();

    // ---- dots: thread (qi, kq) owns keys kj = kk*4 + kq (conflict-free) ----
    int qi = tid >> 2, kq = tid & 3;
    int idq = ids[qi];
    const float* qrow = ks + qi * KSTR;

    float d[32];
#pragma unroll
    for (int half = 0; half < 2; half++) {
        u64 d2[16];
#pragma unroll
        for (int kk = 0; kk < 16; kk++) d2[kk] = 0ull;

        for (int f = 0; f < 16; f++) {
            ulonglong2 qv = *(const ulonglong2*)(qrow + f * 4);
#pragma unroll
            for (int kk = 0; kk < 16; kk++) {
                int kj = ((half << 4) + kk) * 4 + kq;
                ulonglong2 kv = *(const ulonglong2*)(ks + kj * KSTR + f * 4);
                fma2(d2[kk], qv.x, kv.x);
                fma2(d2[kk], qv.y, kv.y);
            }
        }
#pragma unroll
        for (int kk = 0; kk < 16; kk++) {
            int ki = (half << 4) + kk;
            int kj = ki * 4 + kq;
            float val = hadd2(d2[kk]) * invn[kj] * 0.125f;
            if (ids[kj] == idq) val = SELF_VAL;
            d[ki] = val;
        }
    }

    // ---- softmax in registers, reduced across the 4-lane query group -------
    float m = -1e30f;
#pragma unroll
    for (int i = 0; i < 32; i++) m = fmaxf(m, d[i]);
    m = fmaxf(m, __shfl_xor_sync(0xffffffffu, m, 1));
    m = fmaxf(m, __shfl_xor_sync(0xffffffffu, m, 2));

    float s = 0.f;
#pragma unroll
    for (int i = 0; i < 32; i++) { d[i] = __expf(d[i] - m); s += d[i]; }
    s += __shfl_xor_sync(0xffffffffu, s, 1);
    s += __shfl_xor_sync(0xffffffffu, s, 2);
    float inv = 1.0f / s;

#pragma unroll
    for (int kk = 0; kk < 32; kk++) {
        int kj = kk * 4 + kq;
        P[qi * PSTR + kj] = d[kk] * inv;
    }
    if (kq == 0) {
        float lse = m + __logf(s);
        int h = (c * 64 + qi) >> 13;
        g_logits[b * (HH * SS) + h * SS + idq] = lse;
    }
    __syncthreads();

    // ---- PV: thread (qi, dg) owns dims dg*4 + 16k (conflict-free) ----------
    int dg = kq;
    u64 acc[8];
#pragma unroll
    for (int k = 0; k < 8; k++) acc[k] = 0ull;

    const float* prow = P + qi * PSTR;
    for (int jb = 0; jb < 32; jb++) {
        float4 p4 = *(const float4*)(prow + jb * 4);
#pragma unroll
        for (int jj = 0; jj < 4; jj++) {
            int j = jb * 4 + jj;
            float pv = (jj == 0) ? p4.x : (jj == 1) ? p4.y : (jj == 2) ? p4.z : p4.w;
            u64 pp = pack2(pv);
            const float* vrow = vs + j * KSTR;
#pragma unroll
            for (int k = 0; k < 4; k++) {
                ulonglong2 vv = *(const ulonglong2*)(vrow + dg * 4 + 16 * k);
                fma2(acc[2 * k],     pp, vv.x);
                fma2(acc[2 * k + 1], pp, vv.y);
            }
        }
    }

    int h = (c * 64 + qi) >> 13;
    float* optr = g_o + ((size_t)b * (HH * SS) + h * SS + idq) * DD;
#pragma unroll
    for (int k = 0; k < 4; k++) {
        ulonglong2 o;
        o.x = acc[2 * k]; o.y = acc[2 * k + 1];
        *(ulonglong2*)(optr + dg * 4 + 16 * k) = o;
    }
}

// ---------------- kernel 4: combine hash rounds ------------------------------
// grid: B*S*D / 256 = 16384 blocks
__global__ void combine_kernel(float* __restrict__ out)
{
    int gidx = blockIdx.x * 256 + threadIdx.x;   // [0, 4194304)
    int d = gidx & 63;
    int g = gidx >> 6;        // token index within B*S
    int b = g >> 13;
    int s = g & (SS - 1);

    float l[HH];
    float m = -1e30f;
#pragma unroll
    for (int h = 0; h < HH; h++) {
        l[h] = g_logits[b * (HH * SS) + h * SS + s];
        m = fmaxf(m, l[h]);
    }
    float sum = 0.f;
#pragma unroll
    for (int h = 0; h < HH; h++) { l[h] = __expf(l[h] - m); sum += l[h]; }
    float inv = 1.0f / sum;

    float acc = 0.f;
#pragma unroll
    for (int h = 0; h < HH; h++) {
        acc += l[h] * inv * g_o[((size_t)b * (HH * SS) + h * SS + s) * DD + d];
    }
    out[gidx] = acc;
}

// ---------------- launcher ---------------------------------------------------
extern "C" void kernel_launch(void* const* d_in, const int* in_sizes, int n_in,
                              void* d_out, int out_size)
{
    const float* qk  = (const float*)d_in[0];
    const float* v   = (const float*)d_in[1];
    const float* rot = (const float*)d_in[2];
    float* out = (float*)d_out;
    (void)in_sizes; (void)n_in; (void)out_size;

    cudaFuncSetAttribute(attn_kernel,
                         cudaFuncAttributeMaxDynamicSharedMemorySize, ATTN_SMEM);

    hash_kernel<<<BB * HH * (SS / 128), 128>>>(qk, rot);
    sort_kernel<<<BB * HH, 128>>>();
    attn_kernel<<<BB * NCHUNK, 256, ATTN_SMEM>>>(qk, v);
    combine_kernel<<<(BB * SS * DD) / 256, 256>>>(out);
}

// round 3
// speedup vs baseline: 3.5875x; 1.4262x over previous
#include <cuda_runtime.h>
#include <math.h>
#include <stdint.h>

// Problem constants
#define BB 8
#define SS 8192
#define DD 64
#define HH 8
#define NCHUNK 1024          // chunks per batch (H * S / 64)
#define SELF_VAL -5e4f

#define KSTR 68              // K/V row stride in floats (17 float4)
#define PSTR 129             // P row stride in floats (odd -> conflict-free cols)

typedef unsigned long long u64;

// ---------------- packed f32x2 helpers --------------------------------------
__device__ __forceinline__ void fma2(u64& d, u64 a, u64 b) {
    asm("fma.rn.f32x2 %0, %1, %2, %0;" : "+l"(d) : "l"(a), "l"(b));
}
__device__ __forceinline__ u64 pack2(float x) {
    u64 r; unsigned u = __float_as_uint(x);
    asm("mov.b64 %0, {%1, %1};" : "=l"(r) : "r"(u));
    return r;
}
__device__ __forceinline__ float hadd2(u64 a) {
    unsigned lo, hi;
    asm("mov.b64 {%0, %1}, %2;" : "=r"(lo), "=r"(hi) : "l"(a));
    return __uint_as_float(lo) + __uint_as_float(hi);
}

// ---------------- scratch (device globals; no allocations allowed) ----------
__device__ int   g_bucket[BB * HH * SS];                 // 2 MB
__device__ int   g_st[BB * HH * SS];                     // 2 MB  sorted token ids
__device__ float g_logits[BB * HH * SS];                 // 2 MB  per-round lse
__device__ float g_o[(size_t)BB * HH * SS * DD];         // 128 MB per-round outputs

// ---------------- kernel 1: LSH hashing -------------------------------------
// grid: B*H*(S/128) = 4096 blocks, 128 threads (one token per thread)
__global__ void hash_kernel(const float* __restrict__ qk,
                            const float* __restrict__ rot)
{
    __shared__ float rot_s[64 * KSTR];   // rot_s[i][f], padded stride 68

    int blk  = blockIdx.x;
    int tile = blk & 63;
    int h    = (blk >> 6) & 7;
    int b    = blk >> 9;
    int tid  = threadIdx.x;

    // load rotation slice transposed: rot_s[i*68+f] = rotations[f, h, i]
    for (int idx = tid; idx < 4096; idx += 128) {
        int f = idx >> 6, i = idx & 63;
        rot_s[i * KSTR + f] = rot[f * (HH * 64) + h * 64 + i];
    }
    __syncthreads();

    int t = tile * 128 + tid;
    const ulonglong2* q8 = (const ulonglong2*)(qk + ((size_t)b * SS + t) * DD);
    u64 q[32];
#pragma unroll
    for (int k = 0; k < 16; k++) {
        ulonglong2 w = q8[k];
        q[2 * k] = w.x; q[2 * k + 1] = w.y;
    }

    float maxv = -1e30f, minv = 1e30f;
    int maxi = 0, mini = 0;
    for (int i = 0; i < 64; i++) {
        const ulonglong2* rr = (const ulonglong2*)(rot_s + i * KSTR);
        u64 a0 = 0, a1 = 0;
#pragma unroll
        for (int k = 0; k < 16; k++) {
            ulonglong2 r = rr[k];
            fma2(a0, q[2 * k],     r.x);
            fma2(a1, q[2 * k + 1], r.y);
        }
        float vdot = hadd2(a0) + hadd2(a1);
        if (vdot > maxv) { maxv = vdot; maxi = i; }   // strict > keeps first index
        if (vdot < minv) { minv = vdot; mini = i; }
    }
    // argmax over concat([r, -r]): first half wins ties (>=)
    int bucket = (maxv >= -minv) ? maxi : 64 + mini;
    g_bucket[(b * HH + h) * SS + t] = bucket;
}

// ---------------- kernel 2: stable counting sort per (b,h) ------------------
// grid: 64 blocks, 128 threads. Each thread owns a 64-token segment.
__global__ void sort_kernel()
{
    __shared__ unsigned short cnt[128 * 128];  // [segment][bucket]
    __shared__ int tot[128];
    __shared__ int base[128];

    int bh = blockIdx.x;
    const int* gb = g_bucket + bh * SS;
    int* out = g_st + bh * SS;
    int s = threadIdx.x;

    for (int k = 0; k < 128; k++) cnt[s * 128 + k] = 0;
    __syncthreads();

    for (int k = 0; k < 64; k++) {
        int bkt = gb[s * 64 + k];
        cnt[s * 128 + bkt]++;
    }
    __syncthreads();

    // per-bucket exclusive prefix over segments (thread s handles bucket s)
    {
        int run = 0;
        for (int seg = 0; seg < 128; seg++) {
            int vv = cnt[seg * 128 + s];
            cnt[seg * 128 + s] = (unsigned short)run;
            run += vv;
        }
        tot[s] = run;
    }
    __syncthreads();
    if (s == 0) {
        int r = 0;
        for (int k = 0; k < 128; k++) { base[k] = r; r += tot[k]; }
    }
    __syncthreads();

    // stable placement (each thread sequential over its segment)
    for (int k = 0; k < 64; k++) {
        int t = s * 64 + k;
        int bkt = gb[t];
        int pos = base[bkt] + cnt[s * 128 + bkt];
        cnt[s * 128 + bkt]++;
        out[pos] = t;
    }
}

// ---------------- kernel 3: bucketed attention (broadcast scheme) -----------
// grid: B*1024 = 8192 blocks, 256 threads.
// smem floats: ks 128*68 + vs 128*68 + P 64*129 + invn 128 + mred 256 + sred 256
//              + ids 128  = 26432 floats = 105728 B
#define ATTN_SMEM 105728
__global__ void __launch_bounds__(256, 2)
attn_kernel(const float* __restrict__ qk, const float* __restrict__ v)
{
    extern __shared__ float sm[];
    float* ks   = sm;                       // 128 x 68
    float* vs   = ks + 128 * KSTR;          // 128 x 68
    float* P    = vs + 128 * KSTR;          // 64 x 129
    float* invn = P + 64 * PSTR;            // 128
    float* mred = invn + 128;               // 4 x 64
    float* sred = mred + 256;               // 4 x 64
    int*   ids  = (int*)(sred + 256);       // 128

    int b  = blockIdx.x >> 10;
    int c  = blockIdx.x & 1023;
    int pc = (c + NCHUNK - 1) & (NCHUNK - 1);
    int tid = threadIdx.x;
    int w   = tid >> 5;
    int l   = tid & 31;

    if (tid < 128) {
        int p = (tid < 64) ? (c * 64 + tid) : (pc * 64 + (tid - 64));
        ids[tid] = g_st[b * (HH * SS) + p];
    }
    __syncthreads();

    // gather K(=qk rows) and V rows
    const float4* qk4 = (const float4*)(qk + (size_t)b * SS * DD);
    const float4* v4  = (const float4*)(v  + (size_t)b * SS * DD);
    for (int idx = tid; idx < 2048; idx += 256) {
        int r = idx >> 4, f = idx & 15;
        int tok = ids[r];
        ((float4*)ks)[r * 17 + f] = qk4[tok * 16 + f];
        ((float4*)vs)[r * 17 + f] = v4[tok * 16 + f];
    }
    __syncthreads();

    // inverse key norms
    if (tid < 128) {
        const float4* row = (const float4*)ks + tid * 17;
        float ssum = 0.f;
#pragma unroll
        for (int k = 0; k < 16; k++) {
            float4 a = row[k];
            ssum += a.x * a.x + a.y * a.y + a.z * a.z + a.w * a.w;
        }
        invn[tid] = 1.0f / (sqrtf(ssum) + 1e-6f);
    }
    __syncthreads();

    // ---- dots: warp (wq,qh): queries qh*32+l (one per lane), keys wq*32.. --
    // Key/invn/ids reads are warp-uniform -> LDS broadcast (conflict-free).
    int wq = w & 3;
    int qh = w >> 2;
    int qi = qh * 32 + l;
    int kbase = wq * 32;
    int idq = ids[qi];

    ulonglong2 q[16];
    {
        const ulonglong2* qr = (const ulonglong2*)(ks + qi * KSTR);
#pragma unroll
        for (int f = 0; f < 16; f++) q[f] = qr[f];
    }

    float* prow_w = P + qi * PSTR + kbase;
    float m_w = -1e30f;
#pragma unroll 4
    for (int kk = 0; kk < 32; kk++) {
        int kj = kbase + kk;
        const ulonglong2* kr = (const ulonglong2*)(ks + kj * KSTR);
        u64 a0 = 0, a1 = 0, a2 = 0, a3 = 0;
#pragma unroll
        for (int f = 0; f < 16; f += 2) {
            ulonglong2 k0 = kr[f], k1 = kr[f + 1];
            fma2(a0, q[f].x,     k0.x);
            fma2(a1, q[f].y,     k0.y);
            fma2(a2, q[f + 1].x, k1.x);
            fma2(a3, q[f + 1].y, k1.y);
        }
        float val = (hadd2(a0) + hadd2(a1) + hadd2(a2) + hadd2(a3))
                    * invn[kj] * 0.125f;
        if (ids[kj] == idq) val = SELF_VAL;
        prow_w[kk] = val;
        m_w = fmaxf(m_w, val);
    }

    // local exp-sum; store exp(d - m_w) back into P
    float s_w = 0.f;
#pragma unroll
    for (int kk = 0; kk < 32; kk++) {
        float e = __expf(prow_w[kk] - m_w);
        prow_w[kk] = e;
        s_w += e;
    }
    mred[wq * 64 + qi] = m_w;
    sred[wq * 64 + qi] = s_w;
    __syncthreads();

    // merge the 4 key-quarter partials for this query
    float M = -1e30f;
    float mm[4], ss0[4];
#pragma unroll
    for (int t = 0; t < 4; t++) {
        mm[t]  = mred[t * 64 + qi];
        ss0[t] = sred[t * 64 + qi];
        M = fmaxf(M, mm[t]);
    }
    float S = 0.f;
#pragma unroll
    for (int t = 0; t < 4; t++) S += ss0[t] * __expf(mm[t] - M);

    float scale = __expf(m_w - M) / S;
#pragma unroll
    for (int kk = 0; kk < 32; kk++) prow_w[kk] *= scale;

    if (wq == 0) {
        float lse = M + __logf(S);
        int h = (c * 64 + qi) >> 13;
        g_logits[b * (HH * SS) + h * SS + idq] = lse;
    }
    __syncthreads();

    // ---- PV: warp (w&1 -> query half, w>>1 -> 16-dim slice) ----------------
    // P column reads conflict-free (stride 129); V reads broadcast.
    int qi2 = (w & 1) * 32 + l;
    int db  = (w >> 1) * 16;

    u64 acc[8];
#pragma unroll
    for (int k = 0; k < 8; k++) acc[k] = 0ull;

    const float* prow = P + qi2 * PSTR;
#pragma unroll 4
    for (int j = 0; j < 128; j++) {
        u64 pp = pack2(prow[j]);
        const ulonglong2* vr = (const ulonglong2*)(vs + j * KSTR + db);
        ulonglong2 v0 = vr[0], v1 = vr[1], v2 = vr[2], v3 = vr[3];
        fma2(acc[0], pp, v0.x); fma2(acc[1], pp, v0.y);
        fma2(acc[2], pp, v1.x); fma2(acc[3], pp, v1.y);
        fma2(acc[4], pp, v2.x); fma2(acc[5], pp, v2.y);
        fma2(acc[6], pp, v3.x); fma2(acc[7], pp, v3.y);
    }

    int idq2 = ids[qi2];
    int h2 = (c * 64 + qi2) >> 13;
    float* optr = g_o + ((size_t)b * (HH * SS) + h2 * SS + idq2) * DD + db;
#pragma unroll
    for (int k = 0; k < 4; k++) {
        ulonglong2 o;
        o.x = acc[2 * k]; o.y = acc[2 * k + 1];
        *(ulonglong2*)(optr + 4 * k) = o;   // 4 floats per ulonglong2
    }
}

// ---------------- kernel 4: combine hash rounds ------------------------------
// grid: B*S*D / 256 = 16384 blocks
__global__ void combine_kernel(float* __restrict__ out)
{
    int gidx = blockIdx.x * 256 + threadIdx.x;   // [0, 4194304)
    int d = gidx & 63;
    int g = gidx >> 6;        // token index within B*S
    int b = g >> 13;
    int s = g & (SS - 1);

    float l[HH];
    float m = -1e30f;
#pragma unroll
    for (int h = 0; h < HH; h++) {
        l[h] = g_logits[b * (HH * SS) + h * SS + s];
        m = fmaxf(m, l[h]);
    }
    float sum = 0.f;
#pragma unroll
    for (int h = 0; h < HH; h++) { l[h] = __expf(l[h] - m); sum += l[h]; }
    float inv = 1.0f / sum;

    float acc = 0.f;
#pragma unroll
    for (int h = 0; h < HH; h++) {
        acc += l[h] * inv * g_o[((size_t)b * (HH * SS) + h * SS + s) * DD + d];
    }
    out[gidx] = acc;
}

// ---------------- launcher ---------------------------------------------------
extern "C" void kernel_launch(void* const* d_in, const int* in_sizes, int n_in,
                              void* d_out, int out_size)
{
    const float* qk  = (const float*)d_in[0];
    const float* v   = (const float*)d_in[1];
    const float* rot = (const float*)d_in[2];
    float* out = (float*)d_out;
    (void)in_sizes; (void)n_in; (void)out_size;

    cudaFuncSetAttribute(attn_kernel,
                         cudaFuncAttributeMaxDynamicSharedMemorySize, ATTN_SMEM);

    hash_kernel<<<BB * HH * (SS / 128), 128>>>(qk, rot);
    sort_kernel<<<BB * HH, 128>>>();
    attn_kernel<<<BB * NCHUNK, 256, ATTN_SMEM>>>(qk, v);
    combine_kernel<<<(BB * SS * DD) / 256, 256>>>(out);
}

// round 5
// speedup vs baseline: 7.8689x; 2.1934x over previous
#include <cuda_runtime.h>
#include <cuda_fp16.h>
#include <math.h>
#include <stdint.h>

// Problem constants
#define BB 8
#define SS 8192
#define DD 64
#define HH 8
#define NCHUNK 1024
#define SELF_VAL -5e4f
#define KSTR 68

typedef unsigned long long u64;

// ---------------- packed f32x2 helpers (hash kernel) -------------------------
__device__ __forceinline__ void fma2(u64& d, u64 a, u64 b) {
    asm("fma.rn.f32x2 %0, %1, %2, %0;" : "+l"(d) : "l"(a), "l"(b));
}
__device__ __forceinline__ float hadd2(u64 a) {
    unsigned lo, hi;
    asm("mov.b64 {%0, %1}, %2;" : "=r"(lo), "=r"(hi) : "l"(a));
    return __uint_as_float(lo) + __uint_as_float(hi);
}

// ---------------- warp MMA helpers (sm_80-class, compute_103-safe) -----------
__device__ __forceinline__ uint32_t smem_u32(const void* p) {
    uint32_t a;
    asm("{ .reg .u64 t; cvta.to.shared.u64 t, %1; cvt.u32.u64 %0, t; }"
        : "=r"(a) : "l"(p));
    return a;
}
__device__ __forceinline__ void ldm_x4(uint32_t* r, uint32_t addr) {
    asm volatile("ldmatrix.sync.aligned.m8n8.x4.shared.b16 {%0,%1,%2,%3}, [%4];"
                 : "=r"(r[0]), "=r"(r[1]), "=r"(r[2]), "=r"(r[3]) : "r"(addr));
}
__device__ __forceinline__ void ldm_x4t(uint32_t* r, uint32_t addr) {
    asm volatile("ldmatrix.sync.aligned.m8n8.x4.trans.shared.b16 {%0,%1,%2,%3}, [%4];"
                 : "=r"(r[0]), "=r"(r[1]), "=r"(r[2]), "=r"(r[3]) : "r"(addr));
}
__device__ __forceinline__ void mma16816(float* c, const uint32_t* a,
                                         uint32_t b0, uint32_t b1) {
    asm volatile(
        "mma.sync.aligned.m16n8k16.row.col.f32.f16.f16.f32 "
        "{%0,%1,%2,%3}, {%4,%5,%6,%7}, {%8,%9}, {%0,%1,%2,%3};"
        : "+f"(c[0]), "+f"(c[1]), "+f"(c[2]), "+f"(c[3])
        : "r"(a[0]), "r"(a[1]), "r"(a[2]), "r"(a[3]), "r"(b0), "r"(b1));
}

// key-column (0..127) -> tile row (0..191)
__device__ __forceinline__ int kmap(int p, int col) {
    if (p == 0) return (col < 64) ? col : col + 64;
    return (col < 64) ? col + 64 : col - 64;
}

// ---------------- scratch ----------------------------------------------------
__device__ int   g_bucket[BB * HH * SS];
__device__ int   g_st[BB * HH * SS];
__device__ float g_logits[BB * HH * SS];
__device__ float g_o[(size_t)BB * HH * SS * DD];

// ---------------- kernel 1: LSH hashing --------------------------------------
__global__ void hash_kernel(const float* __restrict__ qk,
                            const float* __restrict__ rot)
{
    __shared__ float rot_s[64 * KSTR];

    int blk  = blockIdx.x;
    int tile = blk & 63;
    int h    = (blk >> 6) & 7;
    int b    = blk >> 9;
    int tid  = threadIdx.x;

    for (int idx = tid; idx < 4096; idx += 128) {
        int f = idx >> 6, i = idx & 63;
        rot_s[i * KSTR + f] = rot[f * (HH * 64) + h * 64 + i];
    }
    __syncthreads();

    int t = tile * 128 + tid;
    const ulonglong2* q8 = (const ulonglong2*)(qk + ((size_t)b * SS + t) * DD);
    u64 q[32];
#pragma unroll
    for (int k = 0; k < 16; k++) {
        ulonglong2 w = q8[k];
        q[2 * k] = w.x; q[2 * k + 1] = w.y;
    }

    float maxv = -1e30f, minv = 1e30f;
    int maxi = 0, mini = 0;
    for (int i = 0; i < 64; i++) {
        const ulonglong2* rr = (const ulonglong2*)(rot_s + i * KSTR);
        u64 a0 = 0, a1 = 0;
#pragma unroll
        for (int k = 0; k < 16; k++) {
            ulonglong2 r = rr[k];
            fma2(a0, q[2 * k],     r.x);
            fma2(a1, q[2 * k + 1], r.y);
        }
        float vdot = hadd2(a0) + hadd2(a1);
        if (vdot > maxv) { maxv = vdot; maxi = i; }
        if (vdot < minv) { minv = vdot; mini = i; }
    }
    int bucket = (maxv >= -minv) ? maxi : 64 + mini;
    g_bucket[(b * HH + h) * SS + t] = bucket;
}

// ---------------- kernel 2: stable counting sort per (b,h) -------------------
__global__ void sort_kernel()
{
    __shared__ unsigned short cnt[128 * 128];
    __shared__ int tot[128];
    __shared__ int base[128];

    int bh = blockIdx.x;
    const int* gb = g_bucket + bh * SS;
    int* out = g_st + bh * SS;
    int s = threadIdx.x;

    for (int k = 0; k < 128; k++) cnt[s * 128 + k] = 0;
    __syncthreads();

    for (int k = 0; k < 64; k++) {
        int bkt = gb[s * 64 + k];
        cnt[s * 128 + bkt]++;
    }
    __syncthreads();

    {
        int run = 0;
        for (int seg = 0; seg < 128; seg++) {
            int vv = cnt[seg * 128 + s];
            cnt[seg * 128 + s] = (unsigned short)run;
            run += vv;
        }
        tot[s] = run;
    }
    __syncthreads();
    if (s == 0) {
        int r = 0;
        for (int k = 0; k < 128; k++) { base[k] = r; r += tot[k]; }
    }
    __syncthreads();

    for (int k = 0; k < 64; k++) {
        int t = s * 64 + k;
        int bkt = gb[t];
        int pos = base[bkt] + cnt[s * 128 + bkt];
        cnt[s * 128 + bkt]++;
        out[pos] = t;
    }
}

// ---------------- kernel 3: HMMA bucketed attention --------------------------
// One block = chunk pair (ch0, ch1=ch0+1). Tile rows: [ch0 | ch1 | prev(ch0)].
// Queries = tile rows 0-127.  Problem 0: q rows 0-63, keys cols [own, prev] ->
// tile rows [0-63, 128-191].  Problem 1: q rows 64-127 -> [64-127, 0-63].
#define SM_K    0                       // 192 x 128 B fp16, XOR swizzle
#define SM_V    24576                   // 192 x 128 B fp16, XOR swizzle
#define SM_P    49152                   // 128 rows x 272 B fp16 (padded)
#define SM_INVN 83968                   // 192 f32
#define SM_SSQ  84736                   // 192 f32
#define SM_IDS  85504                   // 192 i32
#define ATTN_SMEM 86272

__global__ void __launch_bounds__(256, 2)
attn_kernel(const float* __restrict__ qk, const float* __restrict__ v)
{
    extern __shared__ char smc[];
    uint32_t sbase = smem_u32(smc);

    float* invn_s = (float*)(smc + SM_INVN);
    float* ssq_s  = (float*)(smc + SM_SSQ);
    int*   ids_s  = (int*)(smc + SM_IDS);

    int blk = blockIdx.x;
    int b   = blk >> 9;
    int t   = blk & 511;
    int ch0 = 2 * t, ch1 = 2 * t + 1;
    int pc0 = (ch0 + NCHUNK - 1) & (NCHUNK - 1);

    int tid = threadIdx.x;
    int w = tid >> 5, l = tid & 31;

    if (tid < 192) {
        int pos = (tid < 64)  ? (ch0 * 64 + tid)
                : (tid < 128) ? (ch1 * 64 + tid - 64)
                              : (pc0 * 64 + tid - 128);
        ids_s[tid] = g_st[b * (HH * SS) + pos];
    }
    __syncthreads();

    // ---- gather + fp32->fp16 + swizzled stores + K row sq-norms -------------
    const float4* qk4 = (const float4*)(qk + (size_t)b * SS * DD);
    const float4* v4  = (const float4*)(v  + (size_t)b * SS * DD);
    for (int i = tid; i < 3072; i += 256) {
        int row = i >> 4, f = i & 15;
        int tok = ids_s[row];
        float4 kx = qk4[(size_t)tok * 16 + f];
        float4 vx = v4[(size_t)tok * 16 + f];
        uint32_t swo = (uint32_t)(row * 128 + f * 8) ^ ((uint32_t)(row & 7) << 4);

        __half2 ka = __floats2half2_rn(kx.x, kx.y);
        __half2 kb = __floats2half2_rn(kx.z, kx.w);
        uint2 kk; kk.x = *(uint32_t*)&ka; kk.y = *(uint32_t*)&kb;
        *(uint2*)(smc + SM_K + swo) = kk;

        __half2 va = __floats2half2_rn(vx.x, vx.y);
        __half2 vb = __floats2half2_rn(vx.z, vx.w);
        uint2 vv; vv.x = *(uint32_t*)&va; vv.y = *(uint32_t*)&vb;
        *(uint2*)(smc + SM_V + swo) = vv;

        float sq = kx.x * kx.x + kx.y * kx.y + kx.z * kx.z + kx.w * kx.w;
        sq += __shfl_xor_sync(0xffffffffu, sq, 1);
        sq += __shfl_xor_sync(0xffffffffu, sq, 2);
        sq += __shfl_xor_sync(0xffffffffu, sq, 4);
        sq += __shfl_xor_sync(0xffffffffu, sq, 8);
        if ((l & 15) == 0) ssq_s[row] = sq;
    }
    __syncthreads();
    if (tid < 192) invn_s[tid] = 1.0f / (sqrtf(ssq_s[tid]) + 1e-6f);
    __syncthreads();

    // ---- scores: warp handles 16 q rows x 128 keys ---------------------------
    int p  = w >> 2;
    int qb = p * 64 + (w & 3) * 16;
    int g  = l >> 2, i4 = l & 3;
    int m8 = l >> 3, rin = l & 7;

    float acc[16][4];
#pragma unroll
    for (int nt = 0; nt < 16; nt++)
#pragma unroll
        for (int k = 0; k < 4; k++) acc[nt][k] = 0.f;

#pragma unroll
    for (int kk = 0; kk < 4; kk++) {
        // A fragment: Q rows qb..+15, dims kk*16..+15
        uint32_t af[4];
        {
            int arow = qb + ((m8 & 1) << 3) + rin;
            int adb  = (kk * 16 + ((m8 >> 1) << 3)) * 2;
            uint32_t aaddr = sbase + SM_K + (uint32_t)(arow * 128)
                           + ((uint32_t)adb ^ ((uint32_t)(arow & 7) << 4));
            ldm_x4(af, aaddr);
        }
#pragma unroll
        for (int jp = 0; jp < 8; jp++) {
            // B: keys (cols 16jp..+15) x dims (kk*16..+15), non-trans
            int keycol = 16 * jp + ((m8 >> 1) << 3) + rin;
            int krow   = kmap(p, keycol);
            int bdb    = (kk * 16 + ((m8 & 1) << 3)) * 2;
            uint32_t baddr = sbase + SM_K + (uint32_t)(krow * 128)
                           + ((uint32_t)bdb ^ ((uint32_t)(krow & 7) << 4));
            uint32_t bf[4];
            ldm_x4(bf, baddr);
            mma16816(acc[2 * jp],     af, bf[0], bf[1]);
            mma16816(acc[2 * jp + 1], af, bf[2], bf[3]);
        }
    }

    // ---- scale + self-mask + warp-local softmax ------------------------------
    int r0 = qb + g, r1 = r0 + 8;
    int id0 = ids_s[r0], id1 = ids_s[r1];

#pragma unroll
    for (int nt = 0; nt < 16; nt++) {
        int ca = 8 * nt + 2 * i4;
        int ka = kmap(p, ca);            // cb = ca+1 -> kb = ka+1 (same half)
        float sa = invn_s[ka] * 0.125f;
        float sb = invn_s[ka + 1] * 0.125f;
        int ia = ids_s[ka], ib = ids_s[ka + 1];
        acc[nt][0] = (ia == id0) ? SELF_VAL : acc[nt][0] * sa;
        acc[nt][1] = (ib == id0) ? SELF_VAL : acc[nt][1] * sb;
        acc[nt][2] = (ia == id1) ? SELF_VAL : acc[nt][2] * sa;
        acc[nt][3] = (ib == id1) ? SELF_VAL : acc[nt][3] * sb;
    }

    float m0 = -1e30f, m1 = -1e30f;
#pragma unroll
    for (int nt = 0; nt < 16; nt++) {
        m0 = fmaxf(m0, fmaxf(acc[nt][0], acc[nt][1]));
        m1 = fmaxf(m1, fmaxf(acc[nt][2], acc[nt][3]));
    }
    m0 = fmaxf(m0, __shfl_xor_sync(0xffffffffu, m0, 1));
    m0 = fmaxf(m0, __shfl_xor_sync(0xffffffffu, m0, 2));
    m1 = fmaxf(m1, __shfl_xor_sync(0xffffffffu, m1, 1));
    m1 = fmaxf(m1, __shfl_xor_sync(0xffffffffu, m1, 2));

    float s0 = 0.f, s1 = 0.f;
#pragma unroll
    for (int nt = 0; nt < 16; nt++) {
        acc[nt][0] = __expf(acc[nt][0] - m0); s0 += acc[nt][0];
        acc[nt][1] = __expf(acc[nt][1] - m0); s0 += acc[nt][1];
        acc[nt][2] = __expf(acc[nt][2] - m1); s1 += acc[nt][2];
        acc[nt][3] = __expf(acc[nt][3] - m1); s1 += acc[nt][3];
    }
    s0 += __shfl_xor_sync(0xffffffffu, s0, 1);
    s0 += __shfl_xor_sync(0xffffffffu, s0, 2);
    s1 += __shfl_xor_sync(0xffffffffu, s1, 1);
    s1 += __shfl_xor_sync(0xffffffffu, s1, 2);
    float inv0 = 1.0f / s0, inv1 = 1.0f / s1;

    int ch = (r0 < 64) ? ch0 : ch1;      // both rows in same 64-half
    int h  = ch >> 7;
    if (i4 == 0) {
        g_logits[b * (HH * SS) + h * SS + id0] = m0 + __logf(s0);
        g_logits[b * (HH * SS) + h * SS + id1] = m1 + __logf(s1);
    }

    // ---- store P (fp16, padded 272B rows) ------------------------------------
#pragma unroll
    for (int nt = 0; nt < 16; nt++) {
        int cb = (8 * nt + 2 * i4) * 2;
        __half2 h0 = __floats2half2_rn(acc[nt][0] * inv0, acc[nt][1] * inv0);
        __half2 h1 = __floats2half2_rn(acc[nt][2] * inv1, acc[nt][3] * inv1);
        *(uint32_t*)(smc + SM_P + r0 * 272 + cb) = *(uint32_t*)&h0;
        *(uint32_t*)(smc + SM_P + r1 * 272 + cb) = *(uint32_t*)&h1;
    }
    __syncwarp();

    // ---- PV: O[16 q x 64 dims] = P[16x128] @ V'[128x64] -----------------------
    float oacc[8][4];
#pragma unroll
    for (int nt = 0; nt < 8; nt++)
#pragma unroll
        for (int k = 0; k < 4; k++) oacc[nt][k] = 0.f;

#pragma unroll
    for (int kk = 0; kk < 8; kk++) {
        uint32_t pa[4];
        {
            int arow = qb + ((m8 & 1) << 3) + rin;
            int acb  = (kk * 16 + ((m8 >> 1) << 3)) * 2;
            ldm_x4(pa, sbase + SM_P + (uint32_t)(arow * 272 + acb));
        }
        int keycol = kk * 16 + ((m8 & 1) << 3) + rin;
        int krow   = kmap(p, keycol);
#pragma unroll
        for (int n2 = 0; n2 < 4; n2++) {
            int vdb = (n2 * 16 + ((m8 >> 1) << 3)) * 2;
            uint32_t vaddr = sbase + SM_V + (uint32_t)(krow * 128)
                           + ((uint32_t)vdb ^ ((uint32_t)(krow & 7) << 4));
            uint32_t vb[4];
            ldm_x4t(vb, vaddr);
            mma16816(oacc[2 * n2],     pa, vb[0], vb[1]);
            mma16816(oacc[2 * n2 + 1], pa, vb[2], vb[3]);
        }
    }

    // ---- write outputs --------------------------------------------------------
    float* o0 = g_o + ((size_t)b * (HH * SS) + (size_t)h * SS + id0) * DD;
    float* o1 = g_o + ((size_t)b * (HH * SS) + (size_t)h * SS + id1) * DD;
#pragma unroll
    for (int nt = 0; nt < 8; nt++) {
        int d = 8 * nt + 2 * i4;
        float2 a; a.x = oacc[nt][0]; a.y = oacc[nt][1];
        float2 c; c.x = oacc[nt][2]; c.y = oacc[nt][3];
        *(float2*)(o0 + d) = a;
        *(float2*)(o1 + d) = c;
    }
}

// ---------------- kernel 4: combine hash rounds -------------------------------
__global__ void combine_kernel(float* __restrict__ out)
{
    int gidx = blockIdx.x * 256 + threadIdx.x;
    int d = gidx & 63;
    int g = gidx >> 6;
    int b = g >> 13;
    int s = g & (SS - 1);

    float lg[HH];
    float m = -1e30f;
#pragma unroll
    for (int h = 0; h < HH; h++) {
        lg[h] = g_logits[b * (HH * SS) + h * SS + s];
        m = fmaxf(m, lg[h]);
    }
    float sum = 0.f;
#pragma unroll
    for (int h = 0; h < HH; h++) { lg[h] = __expf(lg[h] - m); sum += lg[h]; }
    float inv = 1.0f / sum;

    float acc = 0.f;
#pragma unroll
    for (int h = 0; h < HH; h++) {
        acc += lg[h] * inv * g_o[((size_t)b * (HH * SS) + h * SS + s) * DD + d];
    }
    out[gidx] = acc;
}

// ---------------- launcher -----------------------------------------------------
extern "C" void kernel_launch(void* const* d_in, const int* in_sizes, int n_in,
                              void* d_out, int out_size)
{
    const float* qk  = (const float*)d_in[0];
    const float* v   = (const float*)d_in[1];
    const float* rot = (const float*)d_in[2];
    float* out = (float*)d_out;
    (void)in_sizes; (void)n_in; (void)out_size;

    cudaFuncSetAttribute(attn_kernel,
                         cudaFuncAttributeMaxDynamicSharedMemorySize, ATTN_SMEM);

    hash_kernel<<<BB * HH * (SS / 128), 128>>>(qk, rot);
    sort_kernel<<<BB * HH, 128>>>();
    attn_kernel<<<BB * 512, 256, ATTN_SMEM>>>(qk, v);
    combine_kernel<<<(BB * SS * DD) / 256, 256>>>(out);
}

// round 6
// speedup vs baseline: 8.9039x; 1.1315x over previous
#include <cuda_runtime.h>
#include <cuda_fp16.h>
#include <math.h>
#include <stdint.h>

// Problem constants
#define BB 8
#define SS 8192
#define DD 64
#define HH 8
#define NCHUNK 1024
#define SELF_VAL -5e4f
#define KSTR 68

typedef unsigned long long u64;

// ---------------- packed f32x2 helpers (hash kernel) -------------------------
__device__ __forceinline__ void fma2(u64& d, u64 a, u64 b) {
    asm("fma.rn.f32x2 %0, %1, %2, %0;" : "+l"(d) : "l"(a), "l"(b));
}
__device__ __forceinline__ float hadd2(u64 a) {
    unsigned lo, hi;
    asm("mov.b64 {%0, %1}, %2;" : "=r"(lo), "=r"(hi) : "l"(a));
    return __uint_as_float(lo) + __uint_as_float(hi);
}

// ---------------- warp MMA helpers (sm_80-class, compute_103-safe) -----------
__device__ __forceinline__ uint32_t smem_u32(const void* p) {
    uint32_t a;
    asm("{ .reg .u64 t; cvta.to.shared.u64 t, %1; cvt.u32.u64 %0, t; }"
        : "=r"(a) : "l"(p));
    return a;
}
__device__ __forceinline__ void ldm_x4(uint32_t* r, uint32_t addr) {
    asm volatile("ldmatrix.sync.aligned.m8n8.x4.shared.b16 {%0,%1,%2,%3}, [%4];"
                 : "=r"(r[0]), "=r"(r[1]), "=r"(r[2]), "=r"(r[3]) : "r"(addr));
}
__device__ __forceinline__ void ldm_x4t(uint32_t* r, uint32_t addr) {
    asm volatile("ldmatrix.sync.aligned.m8n8.x4.trans.shared.b16 {%0,%1,%2,%3}, [%4];"
                 : "=r"(r[0]), "=r"(r[1]), "=r"(r[2]), "=r"(r[3]) : "r"(addr));
}
__device__ __forceinline__ void mma16816(float* c, const uint32_t* a,
                                         uint32_t b0, uint32_t b1) {
    asm volatile(
        "mma.sync.aligned.m16n8k16.row.col.f32.f16.f16.f32 "
        "{%0,%1,%2,%3}, {%4,%5,%6,%7}, {%8,%9}, {%0,%1,%2,%3};"
        : "+f"(c[0]), "+f"(c[1]), "+f"(c[2]), "+f"(c[3])
        : "r"(a[0]), "r"(a[1]), "r"(a[2]), "r"(a[3]), "r"(b0), "r"(b1));
}
__device__ __forceinline__ uint32_t h2pack(float x, float y) {
    __half2 h = __floats2half2_rn(x, y);
    return *(uint32_t*)&h;
}

// key-column (0..127) -> tile row (0..191)
__device__ __forceinline__ int kmap(int p, int col) {
    if (p == 0) return (col < 64) ? col : col + 64;
    return (col < 64) ? col + 64 : col - 64;
}

// ---------------- scratch ----------------------------------------------------
__device__ int      g_bucket[BB * HH * SS];
__device__ int      g_st[BB * HH * SS];
__device__ float    g_logits[BB * HH * SS];
__device__ uint32_t g_oh[(size_t)BB * HH * SS * 32];   // fp16x2 outputs, 64 MB

// ---------------- kernel 1: LSH hashing --------------------------------------
__global__ void hash_kernel(const float* __restrict__ qk,
                            const float* __restrict__ rot)
{
    __shared__ float rot_s[64 * KSTR];

    int blk  = blockIdx.x;
    int tile = blk & 63;
    int h    = (blk >> 6) & 7;
    int b    = blk >> 9;
    int tid  = threadIdx.x;

    for (int idx = tid; idx < 4096; idx += 128) {
        int f = idx >> 6, i = idx & 63;
        rot_s[i * KSTR + f] = rot[f * (HH * 64) + h * 64 + i];
    }
    __syncthreads();

    int t = tile * 128 + tid;
    const ulonglong2* q8 = (const ulonglong2*)(qk + ((size_t)b * SS + t) * DD);
    u64 q[32];
#pragma unroll
    for (int k = 0; k < 16; k++) {
        ulonglong2 w = q8[k];
        q[2 * k] = w.x; q[2 * k + 1] = w.y;
    }

    float maxv = -1e30f, minv = 1e30f;
    int maxi = 0, mini = 0;
    for (int i = 0; i < 64; i++) {
        const ulonglong2* rr = (const ulonglong2*)(rot_s + i * KSTR);
        u64 a0 = 0, a1 = 0;
#pragma unroll
        for (int k = 0; k < 16; k++) {
            ulonglong2 r = rr[k];
            fma2(a0, q[2 * k],     r.x);
            fma2(a1, q[2 * k + 1], r.y);
        }
        float vdot = hadd2(a0) + hadd2(a1);
        if (vdot > maxv) { maxv = vdot; maxi = i; }
        if (vdot < minv) { minv = vdot; mini = i; }
    }
    int bucket = (maxv >= -minv) ? maxi : 64 + mini;
    g_bucket[(b * HH + h) * SS + t] = bucket;
}

// ---------------- kernel 2: stable counting sort per (b,h) -------------------
__global__ void sort_kernel()
{
    __shared__ unsigned short cnt[128 * 128];
    __shared__ int tot[128];
    __shared__ int base[128];

    int bh = blockIdx.x;
    const int* gb = g_bucket + bh * SS;
    int* out = g_st + bh * SS;
    int s = threadIdx.x;

    for (int k = 0; k < 128; k++) cnt[s * 128 + k] = 0;
    __syncthreads();

    for (int k = 0; k < 64; k++) {
        int bkt = gb[s * 64 + k];
        cnt[s * 128 + bkt]++;
    }
    __syncthreads();

    {
        int run = 0;
        for (int seg = 0; seg < 128; seg++) {
            int vv = cnt[seg * 128 + s];
            cnt[seg * 128 + s] = (unsigned short)run;
            run += vv;
        }
        tot[s] = run;
    }
    __syncthreads();
    if (s == 0) {
        int r = 0;
        for (int k = 0; k < 128; k++) { base[k] = r; r += tot[k]; }
    }
    __syncthreads();

    for (int k = 0; k < 64; k++) {
        int t = s * 64 + k;
        int bkt = gb[t];
        int pos = base[bkt] + cnt[s * 128 + bkt];
        cnt[s * 128 + bkt]++;
        out[pos] = t;
    }
}

// ---------------- kernel 3: HMMA bucketed attention (register P) -------------
// One block = chunk pair (ch0, ch1=ch0+1). Tile rows: [ch0 | ch1 | prev(ch0)].
#define SM_K    0                       // 192 x 128 B fp16, XOR swizzle
#define SM_V    24576                   // 192 x 128 B fp16, XOR swizzle
#define SM_INVN 49152                   // 192 f32
#define SM_SSQ  49920                   // 192 f32
#define SM_IDS  50688                   // 192 i32
#define ATTN_SMEM 51456

__global__ void __launch_bounds__(256, 3)
attn_kernel(const float* __restrict__ qk, const float* __restrict__ v)
{
    extern __shared__ char smc[];
    uint32_t sbase = smem_u32(smc);

    float* invn_s = (float*)(smc + SM_INVN);
    float* ssq_s  = (float*)(smc + SM_SSQ);
    int*   ids_s  = (int*)(smc + SM_IDS);

    int blk = blockIdx.x;
    int b   = blk >> 9;
    int t   = blk & 511;
    int ch0 = 2 * t, ch1 = 2 * t + 1;
    int pc0 = (ch0 + NCHUNK - 1) & (NCHUNK - 1);

    int tid = threadIdx.x;
    int w = tid >> 5, l = tid & 31;

    if (tid < 192) {
        int pos = (tid < 64)  ? (ch0 * 64 + tid)
                : (tid < 128) ? (ch1 * 64 + tid - 64)
                              : (pc0 * 64 + tid - 128);
        ids_s[tid] = g_st[b * (HH * SS) + pos];
    }
    __syncthreads();

    // ---- gather + fp32->fp16 + swizzled stores + K row sq-norms -------------
    const float4* qk4 = (const float4*)(qk + (size_t)b * SS * DD);
    const float4* v4  = (const float4*)(v  + (size_t)b * SS * DD);
    for (int i = tid; i < 3072; i += 256) {
        int row = i >> 4, f = i & 15;
        int tok = ids_s[row];
        float4 kx = qk4[(size_t)tok * 16 + f];
        float4 vx = v4[(size_t)tok * 16 + f];
        uint32_t swo = (uint32_t)(row * 128 + f * 8) ^ ((uint32_t)(row & 7) << 4);

        uint2 kk; kk.x = h2pack(kx.x, kx.y); kk.y = h2pack(kx.z, kx.w);
        *(uint2*)(smc + SM_K + swo) = kk;
        uint2 vv; vv.x = h2pack(vx.x, vx.y); vv.y = h2pack(vx.z, vx.w);
        *(uint2*)(smc + SM_V + swo) = vv;

        float sq = kx.x * kx.x + kx.y * kx.y + kx.z * kx.z + kx.w * kx.w;
        sq += __shfl_xor_sync(0xffffffffu, sq, 1);
        sq += __shfl_xor_sync(0xffffffffu, sq, 2);
        sq += __shfl_xor_sync(0xffffffffu, sq, 4);
        sq += __shfl_xor_sync(0xffffffffu, sq, 8);
        if ((l & 15) == 0) ssq_s[row] = sq;
    }
    __syncthreads();
    if (tid < 192) invn_s[tid] = 1.0f / (sqrtf(ssq_s[tid]) + 1e-6f);
    __syncthreads();

    // ---- scores: warp handles 16 q rows x 128 keys ---------------------------
    int p  = w >> 2;
    int qb = p * 64 + (w & 3) * 16;
    int g  = l >> 2, i4 = l & 3;
    int m8 = l >> 3, rin = l & 7;

    float acc[16][4];
#pragma unroll
    for (int nt = 0; nt < 16; nt++)
#pragma unroll
        for (int k = 0; k < 4; k++) acc[nt][k] = 0.f;

#pragma unroll
    for (int kk = 0; kk < 4; kk++) {
        uint32_t af[4];
        {
            int arow = qb + ((m8 & 1) << 3) + rin;
            int adb  = (kk * 16 + ((m8 >> 1) << 3)) * 2;
            uint32_t aaddr = sbase + SM_K + (uint32_t)(arow * 128)
                           + ((uint32_t)adb ^ ((uint32_t)(arow & 7) << 4));
            ldm_x4(af, aaddr);
        }
#pragma unroll
        for (int jp = 0; jp < 8; jp++) {
            int keycol = 16 * jp + ((m8 >> 1) << 3) + rin;
            int krow   = kmap(p, keycol);
            int bdb    = (kk * 16 + ((m8 & 1) << 3)) * 2;
            uint32_t baddr = sbase + SM_K + (uint32_t)(krow * 128)
                           + ((uint32_t)bdb ^ ((uint32_t)(krow & 7) << 4));
            uint32_t bf[4];
            ldm_x4(bf, baddr);
            mma16816(acc[2 * jp],     af, bf[0], bf[1]);
            mma16816(acc[2 * jp + 1], af, bf[2], bf[3]);
        }
    }

    // ---- scale + self-mask + warp-local softmax ------------------------------
    int r0 = qb + g, r1 = r0 + 8;
    int id0 = ids_s[r0], id1 = ids_s[r1];

#pragma unroll
    for (int nt = 0; nt < 16; nt++) {
        int ca = 8 * nt + 2 * i4;
        int ka = kmap(p, ca);
        float sa = invn_s[ka] * 0.125f;
        float sb = invn_s[ka + 1] * 0.125f;
        int ia = ids_s[ka], ib = ids_s[ka + 1];
        acc[nt][0] = (ia == id0) ? SELF_VAL : acc[nt][0] * sa;
        acc[nt][1] = (ib == id0) ? SELF_VAL : acc[nt][1] * sb;
        acc[nt][2] = (ia == id1) ? SELF_VAL : acc[nt][2] * sa;
        acc[nt][3] = (ib == id1) ? SELF_VAL : acc[nt][3] * sb;
    }

    float m0 = -1e30f, m1 = -1e30f;
#pragma unroll
    for (int nt = 0; nt < 16; nt++) {
        m0 = fmaxf(m0, fmaxf(acc[nt][0], acc[nt][1]));
        m1 = fmaxf(m1, fmaxf(acc[nt][2], acc[nt][3]));
    }
    m0 = fmaxf(m0, __shfl_xor_sync(0xffffffffu, m0, 1));
    m0 = fmaxf(m0, __shfl_xor_sync(0xffffffffu, m0, 2));
    m1 = fmaxf(m1, __shfl_xor_sync(0xffffffffu, m1, 1));
    m1 = fmaxf(m1, __shfl_xor_sync(0xffffffffu, m1, 2));

    // exp + sum + immediate fp16 conversion (P stays in registers, unnormalized)
    float s0 = 0.f, s1 = 0.f;
    uint32_t ph[16][2];
#pragma unroll
    for (int nt = 0; nt < 16; nt++) {
        float e0 = __expf(acc[nt][0] - m0);
        float e1 = __expf(acc[nt][1] - m0);
        float e2 = __expf(acc[nt][2] - m1);
        float e3 = __expf(acc[nt][3] - m1);
        s0 += e0 + e1; s1 += e2 + e3;
        ph[nt][0] = h2pack(e0, e1);      // row g   fragment half
        ph[nt][1] = h2pack(e2, e3);      // row g+8 fragment half
    }
    s0 += __shfl_xor_sync(0xffffffffu, s0, 1);
    s0 += __shfl_xor_sync(0xffffffffu, s0, 2);
    s1 += __shfl_xor_sync(0xffffffffu, s1, 1);
    s1 += __shfl_xor_sync(0xffffffffu, s1, 2);
    float inv0 = 1.0f / s0, inv1 = 1.0f / s1;

    int ch = (r0 < 64) ? ch0 : ch1;
    int h  = ch >> 7;
    if (i4 == 0) {
        g_logits[b * (HH * SS) + h * SS + id0] = m0 + __logf(s0);
        g_logits[b * (HH * SS) + h * SS + id1] = m1 + __logf(s1);
    }

    // ---- PV: A = P fragments straight from registers --------------------------
    float oacc[8][4];
#pragma unroll
    for (int nt = 0; nt < 8; nt++)
#pragma unroll
        for (int k = 0; k < 4; k++) oacc[nt][k] = 0.f;

#pragma unroll
    for (int kk = 0; kk < 8; kk++) {
        uint32_t pa[4];
        pa[0] = ph[2 * kk][0];       // rows g,   keys klo
        pa[1] = ph[2 * kk][1];       // rows g+8, keys klo
        pa[2] = ph[2 * kk + 1][0];   // rows g,   keys khi
        pa[3] = ph[2 * kk + 1][1];   // rows g+8, keys khi
        int keycol = kk * 16 + ((m8 & 1) << 3) + rin;
        int krow   = kmap(p, keycol);
#pragma unroll
        for (int n2 = 0; n2 < 4; n2++) {
            int vdb = (n2 * 16 + ((m8 >> 1) << 3)) * 2;
            uint32_t vaddr = sbase + SM_V + (uint32_t)(krow * 128)
                           + ((uint32_t)vdb ^ ((uint32_t)(krow & 7) << 4));
            uint32_t vb[4];
            ldm_x4t(vb, vaddr);
            mma16816(oacc[2 * n2],     pa, vb[0], vb[1]);
            mma16816(oacc[2 * n2 + 1], pa, vb[2], vb[3]);
        }
    }

    // ---- write outputs (normalize here; fp16x2 packed) ------------------------
    uint32_t* o0 = g_oh + ((size_t)b * (HH * SS) + (size_t)h * SS + id0) * 32;
    uint32_t* o1 = g_oh + ((size_t)b * (HH * SS) + (size_t)h * SS + id1) * 32;
#pragma unroll
    for (int nt = 0; nt < 8; nt++) {
        int dp = 4 * nt + i4;
        o0[dp] = h2pack(oacc[nt][0] * inv0, oacc[nt][1] * inv0);
        o1[dp] = h2pack(oacc[nt][2] * inv1, oacc[nt][3] * inv1);
    }
}

// ---------------- kernel 4: combine hash rounds (fp16 o) ----------------------
// one thread per (token, dim-pair): grid = B*S*32/256
__global__ void combine_kernel(float* __restrict__ out)
{
    int gidx = blockIdx.x * 256 + threadIdx.x;   // [0, 2097152)
    int dp = gidx & 31;
    int g = gidx >> 5;
    int b = g >> 13;
    int s = g & (SS - 1);

    float lg[HH];
    float m = -1e30f;
#pragma unroll
    for (int h = 0; h < HH; h++) {
        lg[h] = g_logits[b * (HH * SS) + h * SS + s];
        m = fmaxf(m, lg[h]);
    }
    float sum = 0.f;
#pragma unroll
    for (int h = 0; h < HH; h++) { lg[h] = __expf(lg[h] - m); sum += lg[h]; }
    float inv = 1.0f / sum;

    float a0 = 0.f, a1 = 0.f;
#pragma unroll
    for (int h = 0; h < HH; h++) {
        uint32_t u = g_oh[((size_t)b * (HH * SS) + h * SS + s) * 32 + dp];
        __half2 hv = *(__half2*)&u;
        float2 f = __half22float2(hv);
        float wgt = lg[h] * inv;
        a0 += wgt * f.x;
        a1 += wgt * f.y;
    }
    float2 r; r.x = a0; r.y = a1;
    *(float2*)(out + ((size_t)b * SS + s) * DD + 2 * dp) = r;
}

// ---------------- launcher -----------------------------------------------------
extern "C" void kernel_launch(void* const* d_in, const int* in_sizes, int n_in,
                              void* d_out, int out_size)
{
    const float* qk  = (const float*)d_in[0];
    const float* v   = (const float*)d_in[1];
    const float* rot = (const float*)d_in[2];
    float* out = (float*)d_out;
    (void)in_sizes; (void)n_in; (void)out_size;

    cudaFuncSetAttribute(attn_kernel,
                         cudaFuncAttributeMaxDynamicSharedMemorySize, ATTN_SMEM);

    hash_kernel<<<BB * HH * (SS / 128), 128>>>(qk, rot);
    sort_kernel<<<BB * HH, 128>>>();
    attn_kernel<<<BB * 512, 256, ATTN_SMEM>>>(qk, v);
    combine_kernel<<<(BB * SS * 32) / 256, 256>>>(out);
}